// round 11
// baseline (speedup 1.0000x reference)
#include <cuda_runtime.h>
#include <cuda_bf16.h>
#include <math_constants.h>
#include <cstdint>

typedef unsigned long long u64;
typedef unsigned int       u32;
typedef unsigned short     u16;

// Problem constants
#define Bb 16
#define Cc 64
#define HW 1024
#define Ntok 16384
#define Kc 8192
#define DECAYF 0.99f
#define ONE_MINUS_DECAYF 0.01f
#define EPSF 1e-5f

// Output layout (float32, reference-return order)
#define O_ZQST 0
#define O_IDX  1048576
#define O_ZQ   1064960
#define O_EMB  2113536
#define O_CS   2637824
#define O_AVG  2646016

// --------------------- scratch (device globals) ------------------------------
__device__ u32   g_Bbf[Kc * 32];    // bf16 codebook, code-major rows of 64 bf16
__device__ float g_enorm[Kc];
__device__ u32   g_maxen;           // bits of max ||e||^2 (positive float)
__device__ int   g_idx[Ntok];
__device__ float g_counts[Kc];
__device__ float g_dw[Kc * Cc];
__device__ float g_n[1];

// --------------------- helpers ----------------------------------------------
__device__ __forceinline__ u32 smem_u32(const void* p) {
    u32 a;
    asm("{ .reg .u64 t; cvta.to.shared.u64 t, %1; cvt.u32.u64 %0, t; }" : "=r"(a) : "l"(p));
    return a;
}
#define CP_ASYNC16(dst, src) \
    asm volatile("cp.async.cg.shared.global [%0], [%1], 16;" :: "r"(dst), "l"(src))
#define CP_COMMIT() asm volatile("cp.async.commit_group;" ::: "memory")
#define CP_WAIT(n)  asm volatile("cp.async.wait_group %0;" :: "n"(n) : "memory")

#define LDMX4(r, addr) \
    asm volatile("ldmatrix.sync.aligned.m8n8.x4.shared.b16 {%0,%1,%2,%3}, [%4];" \
        : "=r"((r)[0]), "=r"((r)[1]), "=r"((r)[2]), "=r"((r)[3]) : "r"(addr))

__device__ __forceinline__ void mma16816(float* d, const u32* a, const u32* b) {
    asm volatile("mma.sync.aligned.m16n8k16.row.col.f32.bf16.bf16.f32 "
        "{%0,%1,%2,%3}, {%4,%5,%6,%7}, {%8,%9}, {%0,%1,%2,%3};"
        : "+f"(d[0]), "+f"(d[1]), "+f"(d[2]), "+f"(d[3])
        : "r"(a[0]), "r"(a[1]), "r"(a[2]), "r"(a[3]), "r"(b[0]), "r"(b[1]));
}

// --------------------- zero / init ------------------------------------------
__global__ void zero_all_kernel() {
    int id = blockIdx.x * blockDim.x + threadIdx.x;
    if (id < Kc * Cc / 4) reinterpret_cast<float4*>(g_dw)[id] = make_float4(0, 0, 0, 0);
    if (id < Kc) g_counts[id] = 0.0f;
    if (id == 0) { g_n[0] = 0.0f; g_maxen = 0u; }
}

// --------------------- prep: ||e||^2 + bf16 codebook (warp per code) ---------
__global__ void __launch_bounds__(256) prep_kernel(const float* __restrict__ emb) {
    int gtid = blockIdx.x * 256 + threadIdx.x;
    int code = gtid >> 5, lane = gtid & 31;
    if (code >= Kc) return;
    float2 e2 = reinterpret_cast<const float2*>(emb + (size_t)code * Cc)[lane];
    u16 h0 = __bfloat16_as_ushort(__float2bfloat16(e2.x));
    u16 h1 = __bfloat16_as_ushort(__float2bfloat16(e2.y));
    g_Bbf[code * 32 + lane] = (u32)h0 | ((u32)h1 << 16);
    float s = e2.x * e2.x + e2.y * e2.y;
#pragma unroll
    for (int off = 16; off >= 1; off >>= 1)
        s += __shfl_xor_sync(0xffffffffu, s, off);
    if (lane == 0) {
        g_enorm[code] = s;
        atomicMax(&g_maxen, __float_as_uint(s));
    }
}

// --------------------- argmin: coarse bf16 GEMM + candidates + fp32 refine ---
// 128 persistent CTAs x 256 threads; CTA owns 128 tokens, scans 64 tiles of 128
// codes. 8 warps each own 16 token-rows (full 128-col tile) via m16n8k16.
#define ROWB 144
#define B_STAGE 18432
#define CAP 64

#define SM_EN     0          // 32768: ||e||^2 fp32
#define SM_ZF     32768      // 34816: z fp32 [128][68]
#define SM_ABF    67584      // 18432: bf16(-2z), 128 rows x 128B, stride 144
#define SM_B      86016      // 2 x 18432: B tiles
#define SM_MARG   122880     // 512: f32 margin per token
#define SM_CNT    123392     // 512: u32 candidate count per token
#define SM_CAND   123904     // 16384: u16 [128][CAP]
#define ARG_SMEM  140288

__global__ void __launch_bounds__(256, 1) argmin_kernel(
    const float* __restrict__ z_e,
    const float* __restrict__ emb)
{
    extern __shared__ char smem[];
    const u32 sb = smem_u32(smem);
    const int tid = threadIdx.x;
    const int lane = tid & 31;
    const int wid = tid >> 5;
    const int gID = lane >> 2, tg = lane & 3;
    const int n0 = blockIdx.x * 128;
    const int b = n0 >> 10, hw0 = n0 & (HW - 1);

    float* en_s = reinterpret_cast<float*>(smem + SM_EN);
    float* zf   = reinterpret_cast<float*>(smem + SM_ZF);
    float* marg = reinterpret_cast<float*>(smem + SM_MARG);
    u32*   cnt  = reinterpret_cast<u32*>(smem + SM_CNT);
    u16*   cand = reinterpret_cast<u16*>(smem + SM_CAND);

    // ---- prologue: en, zf (transposed) ----
    for (int j = tid; j < Kc / 4; j += 256)
        reinterpret_cast<float4*>(en_s)[j] = reinterpret_cast<const float4*>(g_enorm)[j];
    for (int i = tid; i < Cc * 128; i += 256) {
        int c = i >> 7, t = i & 127;
        zf[t * 68 + c] = z_e[(size_t)b * Cc * HW + c * HW + hw0 + t];
    }
    if (tid < 128) cnt[tid] = 0u;
    __syncthreads();

    // bf16(-2z) tile for MMA A operand
    for (int i = tid; i < 128 * 32; i += 256) {
        int t = i >> 5, cp = i & 31;
        float x0 = -2.0f * zf[t * 68 + 2 * cp];
        float x1 = -2.0f * zf[t * 68 + 2 * cp + 1];
        u16 h0 = __bfloat16_as_ushort(__float2bfloat16(x0));
        u16 h1 = __bfloat16_as_ushort(__float2bfloat16(x1));
        reinterpret_cast<u32*>(smem + SM_ABF)[t * 36 + cp] = (u32)h0 | ((u32)h1 << 16);
    }
    // per-token margin: 2E bound for 1-term bf16 coarse distances
    if (tid < 128) {
        float s = 0.0f;
        for (int i = 0; i < Cc; i++) { float v = zf[tid * 68 + i]; s += v * v; }
        float maxe = sqrtf(__uint_as_float(g_maxen));
        marg[tid] = 0.0158f * sqrtf(s) * maxe + 0.003f;
    }
    __syncthreads();

    const int row_lo = wid * 16 + gID;
    const float marg_lo = marg[row_lo];
    const float marg_hi = marg[row_lo + 8];
    float rlo = CUDART_INF_F, rhi = CUDART_INF_F;

    // ---- B tile pipeline ----
    auto loadB = [&](int ct, int s) {
        const char* gB = reinterpret_cast<const char*>(g_Bbf) + (size_t)ct * 128 * 128;
        u32 dst0 = sb + SM_B + s * B_STAGE;
        for (int j = tid; j < 1024; j += 256) {
            int r = j >> 3, c = j & 7;
            CP_ASYNC16(dst0 + r * ROWB + c * 16, gB + r * 128 + c * 16);
        }
    };
    loadB(0, 0);
    CP_COMMIT();

    const u32 aAddr = sb + SM_ABF + (u32)(wid * 16 + (lane & 15)) * ROWB
                    + ((u32)(lane >> 4) << 4);
    const u32 bAddr0 = sb + SM_B + (u32)(lane & 15) * ROWB + ((u32)(lane >> 4) << 4);

    for (int ct = 0; ct < 64; ct++) {
        __syncthreads();                        // prior-iter reads of buf[(ct+1)&1] done
        if (ct + 1 < 64) { loadB(ct + 1, (ct + 1) & 1); CP_COMMIT(); CP_WAIT(1); }
        else             { CP_WAIT(0); }
        __syncthreads();                        // buf[ct&1] visible to all threads

        float d[16][4];
#pragma unroll
        for (int nt = 0; nt < 16; nt++)
#pragma unroll
            for (int i = 0; i < 4; i++) d[nt][i] = 0.0f;

        const u32 bAddr = bAddr0 + (u32)(ct & 1) * B_STAGE;
#pragma unroll
        for (int ks = 0; ks < 4; ks++) {
            u32 a[4];
            LDMX4(a, aAddr + ks * 32);
#pragma unroll
            for (int ntp = 0; ntp < 8; ntp++) {
                u32 bb[4];
                LDMX4(bb, bAddr + ntp * (16 * ROWB) + ks * 32);
                u32 be[2] = { bb[0], bb[2] };
                u32 bo[2] = { bb[1], bb[3] };
                mma16816(d[2 * ntp], a, be);
                mma16816(d[2 * ntp + 1], a, bo);
            }
        }

        // dist = ||e||^2 - 2 z.e; fold row mins (2 shuffles), then candidates
        const float2* ent2 = reinterpret_cast<const float2*>(en_s + ct * 128);
        float tlo = CUDART_INF_F, thi = CUDART_INF_F;
#pragma unroll
        for (int nt = 0; nt < 16; nt++) {
            float2 ee = ent2[nt * 4 + tg];
            d[nt][0] += ee.x; d[nt][1] += ee.y;
            d[nt][2] += ee.x; d[nt][3] += ee.y;
            tlo = fminf(tlo, fminf(d[nt][0], d[nt][1]));
            thi = fminf(thi, fminf(d[nt][2], d[nt][3]));
        }
#pragma unroll
        for (int off = 1; off <= 2; off <<= 1) {
            tlo = fminf(tlo, __shfl_xor_sync(0xffffffffu, tlo, off));
            thi = fminf(thi, __shfl_xor_sync(0xffffffffu, thi, off));
        }
        rlo = fminf(rlo, tlo);
        rhi = fminf(rhi, thi);
        const float thrlo = rlo + marg_lo;
        const float thrhi = rhi + marg_hi;
#pragma unroll
        for (int nt = 0; nt < 16; nt++) {
#pragma unroll
            for (int c = 0; c < 2; c++) {
                int code = ct * 128 + nt * 8 + tg * 2 + c;
                if (d[nt][c] <= thrlo) {
                    u32 pos = atomicAdd(&cnt[row_lo], 1u);
                    if (pos < CAP) cand[row_lo * CAP + pos] = (u16)code;
                }
                if (d[nt][2 + c] <= thrhi) {
                    u32 pos = atomicAdd(&cnt[row_lo + 8], 1u);
                    if (pos < CAP) cand[(row_lo + 8) * CAP + pos] = (u16)code;
                }
            }
        }
    }
    __syncthreads();

    // ---- refine: exact fp32 over candidates (or full scan on overflow) ----
    for (int tt = 0; tt < 16; tt++) {
        int t = wid * 16 + tt;
        u32 n = cnt[t];
        float bv = CUDART_INF_F;
        int bi = 0x7FFFFFFF;
        const float4* zf4 = reinterpret_cast<const float4*>(zf + t * 68);
        if (n <= CAP) {
            for (int j = lane; j < (int)n; j += 32) {
                int c = cand[t * CAP + j];
                const float4* e4 = reinterpret_cast<const float4*>(emb + (size_t)c * Cc);
                float dot = 0.0f;
#pragma unroll
                for (int i = 0; i < 16; i++) {
                    float4 zv = zf4[i], ev = e4[i];
                    dot = fmaf(zv.x, ev.x, dot);
                    dot = fmaf(zv.y, ev.y, dot);
                    dot = fmaf(zv.z, ev.z, dot);
                    dot = fmaf(zv.w, ev.w, dot);
                }
                float v = fmaf(-2.0f, dot, en_s[c]);
                if (v < bv || (v == bv && c < bi)) { bv = v; bi = c; }
            }
        } else {
            for (int c = lane; c < Kc; c += 32) {
                const float4* e4 = reinterpret_cast<const float4*>(emb + (size_t)c * Cc);
                float dot = 0.0f;
#pragma unroll
                for (int i = 0; i < 16; i++) {
                    float4 zv = zf4[i], ev = e4[i];
                    dot = fmaf(zv.x, ev.x, dot);
                    dot = fmaf(zv.y, ev.y, dot);
                    dot = fmaf(zv.z, ev.z, dot);
                    dot = fmaf(zv.w, ev.w, dot);
                }
                float v = fmaf(-2.0f, dot, en_s[c]);
                if (v < bv || (v == bv && c < bi)) { bv = v; bi = c; }
            }
        }
#pragma unroll
        for (int off = 16; off >= 1; off >>= 1) {
            float ov = __shfl_xor_sync(0xffffffffu, bv, off);
            int   oi = __shfl_xor_sync(0xffffffffu, bi, off);
            if (ov < bv || (ov == bv && oi < bi)) { bv = ov; bi = oi; }
        }
        if (lane == 0) g_idx[n0 + t] = bi;
    }
}

// --------------------- EMA scatter (counts, dw) ------------------------------
__global__ void ema_scatter_kernel(const float* __restrict__ z_e) {
    int id = blockIdx.x * blockDim.x + threadIdx.x;   // over Ntok * Cc, n fastest
    if (id >= Ntok * Cc) return;
    int n = id & (Ntok - 1);
    int c = id >> 14;
    int b = n >> 10, hw = n & (HW - 1);
    float v = z_e[(size_t)b * Cc * HW + c * HW + hw];
    int e = g_idx[n];
    atomicAdd(&g_dw[e * Cc + c], v);
    if (c == 0) atomicAdd(&g_counts[e], 1.0f);
}

// --------------------- gather outputs (z_q_st, z_q, indices) -----------------
__global__ void outputs_kernel(const float* __restrict__ z_e,
                               const float* __restrict__ emb,
                               float* __restrict__ out)
{
    int id = blockIdx.x * blockDim.x + threadIdx.x;   // over B*C*H*W / 4
    if (id >= Bb * Cc * HW / 4) return;
    int hwq = id & 255;
    int c   = (id >> 8) & 63;
    int b   = id >> 14;
    int nb  = b * HW + hwq * 4;

    float4 ze = reinterpret_cast<const float4*>(z_e)[id];
    int e0 = g_idx[nb + 0], e1 = g_idx[nb + 1], e2 = g_idx[nb + 2], e3 = g_idx[nb + 3];
    float4 zq;
    zq.x = emb[e0 * Cc + c];
    zq.y = emb[e1 * Cc + c];
    zq.z = emb[e2 * Cc + c];
    zq.w = emb[e3 * Cc + c];
    float4 st;
    st.x = ze.x + (zq.x - ze.x);
    st.y = ze.y + (zq.y - ze.y);
    st.z = ze.z + (zq.z - ze.z);
    st.w = ze.w + (zq.w - ze.w);
    reinterpret_cast<float4*>(out + O_ZQST)[id] = st;
    reinterpret_cast<float4*>(out + O_ZQ)[id]   = zq;

    if (id < Ntok / 4) {
        int n = id * 4;
        float4 ix;
        ix.x = (float)g_idx[n + 0];
        ix.y = (float)g_idx[n + 1];
        ix.z = (float)g_idx[n + 2];
        ix.w = (float)g_idx[n + 3];
        reinterpret_cast<float4*>(out + O_IDX)[id] = ix;
    }
}

// --------------------- EMA blend + n reduction -------------------------------
__global__ void finalize1_kernel(const float* __restrict__ cs_in,
                                 const float* __restrict__ avg_in,
                                 float* __restrict__ out)
{
    int id = blockIdx.x * blockDim.x + threadIdx.x;   // over K*C/4
    if (id >= Kc * Cc / 4) return;
    float4 av = reinterpret_cast<const float4*>(avg_in)[id];
    float4 dw = reinterpret_cast<const float4*>(g_dw)[id];
    float4 r;
    r.x = DECAYF * av.x + ONE_MINUS_DECAYF * dw.x;
    r.y = DECAYF * av.y + ONE_MINUS_DECAYF * dw.y;
    r.z = DECAYF * av.z + ONE_MINUS_DECAYF * dw.z;
    r.w = DECAYF * av.w + ONE_MINUS_DECAYF * dw.w;
    reinterpret_cast<float4*>(out + O_AVG)[id] = r;

    if (id < Kc / 4) {
        float4 cv = reinterpret_cast<const float4*>(cs_in)[id];
        float4 ct = reinterpret_cast<const float4*>(g_counts)[id];
        float4 cs;
        cs.x = DECAYF * cv.x + ONE_MINUS_DECAYF * ct.x;
        cs.y = DECAYF * cv.y + ONE_MINUS_DECAYF * ct.y;
        cs.z = DECAYF * cv.z + ONE_MINUS_DECAYF * ct.z;
        cs.w = DECAYF * cv.w + ONE_MINUS_DECAYF * ct.w;
        reinterpret_cast<float4*>(out + O_CS)[id] = cs;
        float local = cs.x + cs.y + cs.z + cs.w;
#pragma unroll
        for (int off = 16; off >= 1; off >>= 1)
            local += __shfl_xor_sync(0xffffffffu, local, off);
        if ((threadIdx.x & 31) == 0) atomicAdd(g_n, local);
    }
}

// --------------------- normalized embedding ----------------------------------
__global__ void finalize2_kernel(float* __restrict__ out) {
    int id = blockIdx.x * blockDim.x + threadIdx.x;   // over K*C/4
    if (id >= Kc * Cc / 4) return;
    int k = id >> 4;
    float n = g_n[0];
    float csv = out[O_CS + k];
    float cs = (csv + EPSF) / (n + (float)Kc * EPSF) * n;
    float inv = 1.0f / cs;
    float4 av = reinterpret_cast<const float4*>(out + O_AVG)[id];
    float4 r;
    r.x = av.x * inv; r.y = av.y * inv; r.z = av.z * inv; r.w = av.w * inv;
    reinterpret_cast<float4*>(out + O_EMB)[id] = r;
}

// --------------------- launcher ---------------------------------------------
extern "C" void kernel_launch(void* const* d_in, const int* in_sizes, int n_in,
                              void* d_out, int out_size)
{
    const float* z_e = (const float*)d_in[0];
    const float* emb = (const float*)d_in[1];
    const float* cs  = (const float*)d_in[2];
    const float* avg = (const float*)d_in[3];
    float* out = (float*)d_out;

    cudaFuncSetAttribute(argmin_kernel,
                         cudaFuncAttributeMaxDynamicSharedMemorySize, ARG_SMEM);

    zero_all_kernel<<<(Kc * Cc / 4 + 255) / 256, 256>>>();
    prep_kernel<<<Kc * 32 / 256, 256>>>(emb);
    argmin_kernel<<<Ntok / 128, 256, ARG_SMEM>>>(z_e, emb);
    ema_scatter_kernel<<<(Ntok * Cc + 255) / 256, 256>>>(z_e);
    outputs_kernel<<<(Bb * Cc * HW / 4 + 255) / 256, 256>>>(z_e, emb, out);
    finalize1_kernel<<<(Kc * Cc / 4 + 255) / 256, 256>>>(cs, avg, out);
    finalize2_kernel<<<(Kc * Cc / 4 + 255) / 256, 256>>>(out);
}

// round 12
// speedup vs baseline: 1.7013x; 1.7013x over previous
#include <cuda_runtime.h>
#include <cuda_bf16.h>
#include <math_constants.h>
#include <cstdint>

typedef unsigned long long u64;
typedef unsigned int       u32;
typedef unsigned short     u16;

// Problem constants
#define Bb 16
#define Cc 64
#define HW 1024
#define Ntok 16384
#define Kc 8192
#define DECAYF 0.99f
#define ONE_MINUS_DECAYF 0.01f
#define EPSF 1e-5f

// Output layout (float32, reference-return order)
#define O_ZQST 0
#define O_IDX  1048576
#define O_ZQ   1064960
#define O_EMB  2113536
#define O_CS   2637824
#define O_AVG  2646016

// --------------------- scratch (device globals) ------------------------------
__device__ u32   g_Bbf[Kc * 32];    // bf16 codebook, code-major rows of 64 bf16
__device__ float g_enorm[Kc];
__device__ u32   g_maxen;           // bits of max ||e||^2 (positive float)
__device__ int   g_idx[Ntok];
__device__ float g_counts[Kc];
__device__ float g_dw[Kc * Cc];
__device__ float g_n[1];

// --------------------- helpers ----------------------------------------------
__device__ __forceinline__ u32 smem_u32(const void* p) {
    u32 a;
    asm("{ .reg .u64 t; cvta.to.shared.u64 t, %1; cvt.u32.u64 %0, t; }" : "=r"(a) : "l"(p));
    return a;
}
#define CP_ASYNC16(dst, src) \
    asm volatile("cp.async.cg.shared.global [%0], [%1], 16;" :: "r"(dst), "l"(src))
#define CP_COMMIT() asm volatile("cp.async.commit_group;" ::: "memory")
#define CP_WAIT(n)  asm volatile("cp.async.wait_group %0;" :: "n"(n) : "memory")

#define LDMX4(r, addr) \
    asm volatile("ldmatrix.sync.aligned.m8n8.x4.shared.b16 {%0,%1,%2,%3}, [%4];" \
        : "=r"((r)[0]), "=r"((r)[1]), "=r"((r)[2]), "=r"((r)[3]) : "r"(addr))

__device__ __forceinline__ void mma16816(float* d, const u32* a, const u32* b) {
    asm volatile("mma.sync.aligned.m16n8k16.row.col.f32.bf16.bf16.f32 "
        "{%0,%1,%2,%3}, {%4,%5,%6,%7}, {%8,%9}, {%0,%1,%2,%3};"
        : "+f"(d[0]), "+f"(d[1]), "+f"(d[2]), "+f"(d[3])
        : "r"(a[0]), "r"(a[1]), "r"(a[2]), "r"(a[3]), "r"(b[0]), "r"(b[1]));
}

// --------------------- zero / init ------------------------------------------
__global__ void zero_all_kernel() {
    int id = blockIdx.x * blockDim.x + threadIdx.x;
    if (id < Kc * Cc / 4) reinterpret_cast<float4*>(g_dw)[id] = make_float4(0, 0, 0, 0);
    if (id < Kc) g_counts[id] = 0.0f;
    if (id == 0) { g_n[0] = 0.0f; g_maxen = 0u; }
}

// --------------------- prep: ||e||^2 + bf16 codebook (warp per code) ---------
__global__ void __launch_bounds__(256) prep_kernel(const float* __restrict__ emb) {
    int gtid = blockIdx.x * 256 + threadIdx.x;
    int code = gtid >> 5, lane = gtid & 31;
    if (code >= Kc) return;
    float2 e2 = reinterpret_cast<const float2*>(emb + (size_t)code * Cc)[lane];
    u16 h0 = __bfloat16_as_ushort(__float2bfloat16(e2.x));
    u16 h1 = __bfloat16_as_ushort(__float2bfloat16(e2.y));
    g_Bbf[code * 32 + lane] = (u32)h0 | ((u32)h1 << 16);
    float s = e2.x * e2.x + e2.y * e2.y;
#pragma unroll
    for (int off = 16; off >= 1; off >>= 1)
        s += __shfl_xor_sync(0xffffffffu, s, off);
    if (lane == 0) {
        g_enorm[code] = s;
        atomicMax(&g_maxen, __float_as_uint(s));
    }
}

// --------------------- argmin: coarse bf16 GEMM + candidates + fp32 refine ---
// 128 persistent CTAs x 256 threads; CTA owns 128 tokens, scans 64 tiles of 128
// codes. 8 warps as 4(m) x 2(n); warp tile 32x64 via m16n8k16 + ldmatrix.
// 4-stage cp.async pipeline, ONE barrier per tile. Threshold = per-warp-half
// running row-min (>= global min => candidate superset preserved).
#define ROWB 144
#define B_STAGE 18432
#define CAP 64

#define SM_EN     0          // 32768: ||e||^2 fp32
#define SM_ZF     32768      // 34816: z fp32 [128][68]
#define SM_ABF    67584      // 18432: bf16(-2z), 128 rows x 128B, stride 144
#define SM_B      86016      // 4 x 18432 stages
#define SM_MARG   159744     // 512
#define SM_CNT    160256     // 512
#define SM_CAND   160768     // 16384: u16 [128][CAP]
#define ARG_SMEM  177152

__global__ void __launch_bounds__(256, 1) argmin_kernel(
    const float* __restrict__ z_e,
    const float* __restrict__ emb)
{
    extern __shared__ char smem[];
    const u32 sb = smem_u32(smem);
    const int tid = threadIdx.x;
    const int lane = tid & 31;
    const int wid = tid >> 5;
    const int warp_m = wid >> 1, warp_n = wid & 1;
    const int gID = lane >> 2, tg = lane & 3;
    const int n0 = blockIdx.x * 128;
    const int b = n0 >> 10, hw0 = n0 & (HW - 1);

    float* en_s = reinterpret_cast<float*>(smem + SM_EN);
    float* zf   = reinterpret_cast<float*>(smem + SM_ZF);
    float* marg = reinterpret_cast<float*>(smem + SM_MARG);
    u32*   cnt  = reinterpret_cast<u32*>(smem + SM_CNT);
    u16*   cand = reinterpret_cast<u16*>(smem + SM_CAND);

    // ---- prologue: en, zf (transposed) ----
    for (int j = tid; j < Kc / 4; j += 256)
        reinterpret_cast<float4*>(en_s)[j] = reinterpret_cast<const float4*>(g_enorm)[j];
    for (int i = tid; i < Cc * 128; i += 256) {
        int c = i >> 7, t = i & 127;
        zf[t * 68 + c] = z_e[(size_t)b * Cc * HW + c * HW + hw0 + t];
    }
    if (tid < 128) cnt[tid] = 0u;
    __syncthreads();

    // bf16(-2z) tile for MMA A operand
    for (int i = tid; i < 128 * 32; i += 256) {
        int t = i >> 5, cp = i & 31;
        float x0 = -2.0f * zf[t * 68 + 2 * cp];
        float x1 = -2.0f * zf[t * 68 + 2 * cp + 1];
        u16 h0 = __bfloat16_as_ushort(__float2bfloat16(x0));
        u16 h1 = __bfloat16_as_ushort(__float2bfloat16(x1));
        reinterpret_cast<u32*>(smem + SM_ABF)[t * 36 + cp] = (u32)h0 | ((u32)h1 << 16);
    }
    // per-token margin: 2E bound for 1-term bf16 coarse distances
    if (tid < 128) {
        float s = 0.0f;
        for (int i = 0; i < Cc; i++) { float v = zf[tid * 68 + i]; s += v * v; }
        float maxe = sqrtf(__uint_as_float(g_maxen));
        marg[tid] = 0.0158f * sqrtf(s) * maxe + 0.003f;
    }

    // ---- 4-stage B pipeline ----
    auto loadB = [&](int ct, int s) {
        const char* gB = reinterpret_cast<const char*>(g_Bbf) + (size_t)ct * 128 * 128;
        u32 dst0 = sb + SM_B + s * B_STAGE;
        for (int j = tid; j < 1024; j += 256) {
            int r = j >> 3, c = j & 7;
            CP_ASYNC16(dst0 + r * ROWB + c * 16, gB + r * 128 + c * 16);
        }
    };
    loadB(0, 0); CP_COMMIT();
    loadB(1, 1); CP_COMMIT();
    loadB(2, 2); CP_COMMIT();
    __syncthreads();                      // marg/ABF visible before first use

    // per-warp running row-mins + margins (rows: warp_m*32 + mt*16 + h*8 + gID)
    float rmin[2][2], mg[2][2];
#pragma unroll
    for (int mt = 0; mt < 2; mt++)
#pragma unroll
        for (int h = 0; h < 2; h++) {
            rmin[mt][h] = CUDART_INF_F;
            mg[mt][h] = marg[warp_m * 32 + mt * 16 + h * 8 + gID];
        }

    const u32 aAddr0 = sb + SM_ABF + (u32)(warp_m * 32 + (lane & 15)) * ROWB
                     + ((u32)(lane >> 4) << 4);
    const u32 bAddrS = (u32)(warp_n * 64 + (lane & 15)) * ROWB + ((u32)(lane >> 4) << 4);

    for (int ct = 0; ct < 64; ct++) {
        CP_WAIT(2);
        __syncthreads();   // stage ct&3 visible to all; prev compute fully done

        float d[2][8][4];
#pragma unroll
        for (int mt = 0; mt < 2; mt++)
#pragma unroll
            for (int nt = 0; nt < 8; nt++)
#pragma unroll
                for (int i = 0; i < 4; i++) d[mt][nt][i] = 0.0f;

        const u32 bAddr = sb + SM_B + (u32)(ct & 3) * B_STAGE + bAddrS;
#pragma unroll
        for (int ks = 0; ks < 4; ks++) {
            u32 a[2][4];
            LDMX4(a[0], aAddr0 + ks * 32);
            LDMX4(a[1], aAddr0 + 16 * ROWB + ks * 32);
#pragma unroll
            for (int ntp = 0; ntp < 4; ntp++) {
                u32 bb[4];
                LDMX4(bb, bAddr + ntp * (16 * ROWB) + ks * 32);
                u32 be[2] = { bb[0], bb[2] };
                u32 bo[2] = { bb[1], bb[3] };
                mma16816(d[0][2 * ntp],     a[0], be);
                mma16816(d[0][2 * ntp + 1], a[0], bo);
                mma16816(d[1][2 * ntp],     a[1], be);
                mma16816(d[1][2 * ntp + 1], a[1], bo);
            }
        }

        // epilogue: add ||e||^2, fold local row-min (2 shuffles), candidates
        const float2* ent2 = reinterpret_cast<const float2*>(en_s + ct * 128 + warp_n * 64);
#pragma unroll
        for (int mt = 0; mt < 2; mt++) {
            float m0 = CUDART_INF_F, m1 = CUDART_INF_F;
#pragma unroll
            for (int nt = 0; nt < 8; nt++) {
                float2 ee = ent2[nt * 4 + tg];
                d[mt][nt][0] += ee.x; d[mt][nt][1] += ee.y;
                d[mt][nt][2] += ee.x; d[mt][nt][3] += ee.y;
                m0 = fminf(m0, fminf(d[mt][nt][0], d[mt][nt][1]));
                m1 = fminf(m1, fminf(d[mt][nt][2], d[mt][nt][3]));
            }
#pragma unroll
            for (int off = 1; off <= 2; off <<= 1) {
                m0 = fminf(m0, __shfl_xor_sync(0xffffffffu, m0, off));
                m1 = fminf(m1, __shfl_xor_sync(0xffffffffu, m1, off));
            }
            rmin[mt][0] = fminf(rmin[mt][0], m0);
            rmin[mt][1] = fminf(rmin[mt][1], m1);
            const float thr0 = rmin[mt][0] + mg[mt][0];
            const float thr1 = rmin[mt][1] + mg[mt][1];
            const int row0 = warp_m * 32 + mt * 16 + gID;
#pragma unroll
            for (int nt = 0; nt < 8; nt++) {
#pragma unroll
                for (int c = 0; c < 2; c++) {
                    int code = ct * 128 + warp_n * 64 + nt * 8 + tg * 2 + c;
                    if (d[mt][nt][c] <= thr0) {
                        u32 pos = atomicAdd(&cnt[row0], 1u);
                        if (pos < CAP) cand[row0 * CAP + pos] = (u16)code;
                    }
                    if (d[mt][nt][2 + c] <= thr1) {
                        u32 pos = atomicAdd(&cnt[row0 + 8], 1u);
                        if (pos < CAP) cand[(row0 + 8) * CAP + pos] = (u16)code;
                    }
                }
            }
        }

        if (ct + 3 < 64) { loadB(ct + 3, (ct + 3) & 3); CP_COMMIT(); }
    }
    __syncthreads();

    // ---- refine: exact fp32 over candidates (or full scan on overflow) ----
    for (int tt = 0; tt < 16; tt++) {
        int t = wid * 16 + tt;
        u32 n = cnt[t];
        float bv = CUDART_INF_F;
        int bi = 0x7FFFFFFF;
        const float4* zf4 = reinterpret_cast<const float4*>(zf + t * 68);
        if (n <= CAP) {
            for (int j = lane; j < (int)n; j += 32) {
                int c = cand[t * CAP + j];
                const float4* e4 = reinterpret_cast<const float4*>(emb + (size_t)c * Cc);
                float dot = 0.0f;
#pragma unroll
                for (int i = 0; i < 16; i++) {
                    float4 zv = zf4[i], ev = e4[i];
                    dot = fmaf(zv.x, ev.x, dot);
                    dot = fmaf(zv.y, ev.y, dot);
                    dot = fmaf(zv.z, ev.z, dot);
                    dot = fmaf(zv.w, ev.w, dot);
                }
                float v = fmaf(-2.0f, dot, en_s[c]);
                if (v < bv || (v == bv && c < bi)) { bv = v; bi = c; }
            }
        } else {
            for (int c = lane; c < Kc; c += 32) {
                const float4* e4 = reinterpret_cast<const float4*>(emb + (size_t)c * Cc);
                float dot = 0.0f;
#pragma unroll
                for (int i = 0; i < 16; i++) {
                    float4 zv = zf4[i], ev = e4[i];
                    dot = fmaf(zv.x, ev.x, dot);
                    dot = fmaf(zv.y, ev.y, dot);
                    dot = fmaf(zv.z, ev.z, dot);
                    dot = fmaf(zv.w, ev.w, dot);
                }
                float v = fmaf(-2.0f, dot, en_s[c]);
                if (v < bv || (v == bv && c < bi)) { bv = v; bi = c; }
            }
        }
#pragma unroll
        for (int off = 16; off >= 1; off >>= 1) {
            float ov = __shfl_xor_sync(0xffffffffu, bv, off);
            int   oi = __shfl_xor_sync(0xffffffffu, bi, off);
            if (ov < bv || (ov == bv && oi < bi)) { bv = ov; bi = oi; }
        }
        if (lane == 0) g_idx[n0 + t] = bi;
    }
}

// --------------------- EMA scatter (counts, dw) ------------------------------
__global__ void ema_scatter_kernel(const float* __restrict__ z_e) {
    int id = blockIdx.x * blockDim.x + threadIdx.x;   // over Ntok * Cc, n fastest
    if (id >= Ntok * Cc) return;
    int n = id & (Ntok - 1);
    int c = id >> 14;
    int b = n >> 10, hw = n & (HW - 1);
    float v = z_e[(size_t)b * Cc * HW + c * HW + hw];
    int e = g_idx[n];
    atomicAdd(&g_dw[e * Cc + c], v);
    if (c == 0) atomicAdd(&g_counts[e], 1.0f);
}

// --------------------- gather outputs (z_q_st, z_q, indices) -----------------
__global__ void outputs_kernel(const float* __restrict__ z_e,
                               const float* __restrict__ emb,
                               float* __restrict__ out)
{
    int id = blockIdx.x * blockDim.x + threadIdx.x;   // over B*C*H*W / 4
    if (id >= Bb * Cc * HW / 4) return;
    int hwq = id & 255;
    int c   = (id >> 8) & 63;
    int b   = id >> 14;
    int nb  = b * HW + hwq * 4;

    float4 ze = reinterpret_cast<const float4*>(z_e)[id];
    int e0 = g_idx[nb + 0], e1 = g_idx[nb + 1], e2 = g_idx[nb + 2], e3 = g_idx[nb + 3];
    float4 zq;
    zq.x = emb[e0 * Cc + c];
    zq.y = emb[e1 * Cc + c];
    zq.z = emb[e2 * Cc + c];
    zq.w = emb[e3 * Cc + c];
    float4 st;
    st.x = ze.x + (zq.x - ze.x);
    st.y = ze.y + (zq.y - ze.y);
    st.z = ze.z + (zq.z - ze.z);
    st.w = ze.w + (zq.w - ze.w);
    reinterpret_cast<float4*>(out + O_ZQST)[id] = st;
    reinterpret_cast<float4*>(out + O_ZQ)[id]   = zq;

    if (id < Ntok / 4) {
        int n = id * 4;
        float4 ix;
        ix.x = (float)g_idx[n + 0];
        ix.y = (float)g_idx[n + 1];
        ix.z = (float)g_idx[n + 2];
        ix.w = (float)g_idx[n + 3];
        reinterpret_cast<float4*>(out + O_IDX)[id] = ix;
    }
}

// --------------------- EMA blend + n reduction -------------------------------
__global__ void finalize1_kernel(const float* __restrict__ cs_in,
                                 const float* __restrict__ avg_in,
                                 float* __restrict__ out)
{
    int id = blockIdx.x * blockDim.x + threadIdx.x;   // over K*C/4
    if (id >= Kc * Cc / 4) return;
    float4 av = reinterpret_cast<const float4*>(avg_in)[id];
    float4 dw = reinterpret_cast<const float4*>(g_dw)[id];
    float4 r;
    r.x = DECAYF * av.x + ONE_MINUS_DECAYF * dw.x;
    r.y = DECAYF * av.y + ONE_MINUS_DECAYF * dw.y;
    r.z = DECAYF * av.z + ONE_MINUS_DECAYF * dw.z;
    r.w = DECAYF * av.w + ONE_MINUS_DECAYF * dw.w;
    reinterpret_cast<float4*>(out + O_AVG)[id] = r;

    if (id < Kc / 4) {
        float4 cv = reinterpret_cast<const float4*>(cs_in)[id];
        float4 ct = reinterpret_cast<const float4*>(g_counts)[id];
        float4 cs;
        cs.x = DECAYF * cv.x + ONE_MINUS_DECAYF * ct.x;
        cs.y = DECAYF * cv.y + ONE_MINUS_DECAYF * ct.y;
        cs.z = DECAYF * cv.z + ONE_MINUS_DECAYF * ct.z;
        cs.w = DECAYF * cv.w + ONE_MINUS_DECAYF * ct.w;
        reinterpret_cast<float4*>(out + O_CS)[id] = cs;
        float local = cs.x + cs.y + cs.z + cs.w;
#pragma unroll
        for (int off = 16; off >= 1; off >>= 1)
            local += __shfl_xor_sync(0xffffffffu, local, off);
        if ((threadIdx.x & 31) == 0) atomicAdd(g_n, local);
    }
}

// --------------------- normalized embedding ----------------------------------
__global__ void finalize2_kernel(float* __restrict__ out) {
    int id = blockIdx.x * blockDim.x + threadIdx.x;   // over K*C/4
    if (id >= Kc * Cc / 4) return;
    int k = id >> 4;
    float n = g_n[0];
    float csv = out[O_CS + k];
    float cs = (csv + EPSF) / (n + (float)Kc * EPSF) * n;
    float inv = 1.0f / cs;
    float4 av = reinterpret_cast<const float4*>(out + O_AVG)[id];
    float4 r;
    r.x = av.x * inv; r.y = av.y * inv; r.z = av.z * inv; r.w = av.w * inv;
    reinterpret_cast<float4*>(out + O_EMB)[id] = r;
}

// --------------------- launcher ---------------------------------------------
extern "C" void kernel_launch(void* const* d_in, const int* in_sizes, int n_in,
                              void* d_out, int out_size)
{
    const float* z_e = (const float*)d_in[0];
    const float* emb = (const float*)d_in[1];
    const float* cs  = (const float*)d_in[2];
    const float* avg = (const float*)d_in[3];
    float* out = (float*)d_out;

    cudaFuncSetAttribute(argmin_kernel,
                         cudaFuncAttributeMaxDynamicSharedMemorySize, ARG_SMEM);

    zero_all_kernel<<<(Kc * Cc / 4 + 255) / 256, 256>>>();
    prep_kernel<<<Kc * 32 / 256, 256>>>(emb);
    argmin_kernel<<<Ntok / 128, 256, ARG_SMEM>>>(z_e, emb);
    ema_scatter_kernel<<<(Ntok * Cc + 255) / 256, 256>>>(z_e);
    outputs_kernel<<<(Bb * Cc * HW / 4 + 255) / 256, 256>>>(z_e, emb, out);
    finalize1_kernel<<<(Kc * Cc / 4 + 255) / 256, 256>>>(cs, avg, out);
    finalize2_kernel<<<(Kc * Cc / 4 + 255) / 256, 256>>>(out);
}

// round 14
// speedup vs baseline: 1.7549x; 1.0315x over previous
#include <cuda_runtime.h>
#include <cuda_bf16.h>
#include <math_constants.h>
#include <cstdint>

typedef unsigned long long u64;
typedef unsigned int       u32;
typedef unsigned short     u16;

// Problem constants
#define Bb 16
#define Cc 64
#define HW 1024
#define Ntok 16384
#define Kc 8192
#define DECAYF 0.99f
#define ONE_MINUS_DECAYF 0.01f
#define EPSF 1e-5f

// Output layout (float32, reference-return order)
#define O_ZQST 0
#define O_IDX  1048576
#define O_ZQ   1064960
#define O_EMB  2113536
#define O_CS   2637824
#define O_AVG  2646016

// --------------------- scratch (device globals) ------------------------------
__device__ u32   g_Bbf[Kc * 32];    // bf16 codebook, code-major rows of 64 bf16
__device__ float g_enorm[Kc];
__device__ u32   g_maxen;           // bits of max ||e||^2 (positive float)
__device__ float g_counts[Kc];
__device__ float g_dw[Kc * Cc];
__device__ float g_n[1];

// --------------------- helpers ----------------------------------------------
__device__ __forceinline__ u32 smem_u32(const void* p) {
    u32 a;
    asm("{ .reg .u64 t; cvta.to.shared.u64 t, %1; cvt.u32.u64 %0, t; }" : "=r"(a) : "l"(p));
    return a;
}
#define CP_ASYNC16(dst, src) \
    asm volatile("cp.async.cg.shared.global [%0], [%1], 16;" :: "r"(dst), "l"(src))
#define CP_COMMIT() asm volatile("cp.async.commit_group;" ::: "memory")
#define CP_WAIT(n)  asm volatile("cp.async.wait_group %0;" :: "n"(n) : "memory")

#define LDMX4(r, addr) \
    asm volatile("ldmatrix.sync.aligned.m8n8.x4.shared.b16 {%0,%1,%2,%3}, [%4];" \
        : "=r"((r)[0]), "=r"((r)[1]), "=r"((r)[2]), "=r"((r)[3]) : "r"(addr))

__device__ __forceinline__ void mma16816(float* d, const u32* a, const u32* b) {
    asm volatile("mma.sync.aligned.m16n8k16.row.col.f32.bf16.bf16.f32 "
        "{%0,%1,%2,%3}, {%4,%5,%6,%7}, {%8,%9}, {%0,%1,%2,%3};"
        : "+f"(d[0]), "+f"(d[1]), "+f"(d[2]), "+f"(d[3])
        : "r"(a[0]), "r"(a[1]), "r"(a[2]), "r"(a[3]), "r"(b[0]), "r"(b[1]));
}

// --------------------- prep: zero scratch + ||e||^2 + bf16 codebook ----------
// grid = 1024 x 256 threads (warp per code for the codebook part)
__global__ void __launch_bounds__(256) prep_kernel(const float* __restrict__ emb) {
    int gtid = blockIdx.x * 256 + threadIdx.x;
    // zero g_dw (131072 float4), g_counts, g_n
    if (gtid < Kc * Cc / 4) reinterpret_cast<float4*>(g_dw)[gtid] = make_float4(0, 0, 0, 0);
    if (gtid < Kc) g_counts[gtid] = 0.0f;
    if (gtid == 0) { g_n[0] = 0.0f; g_maxen = 0u; }

    int code = gtid >> 5, lane = gtid & 31;
    if (code >= Kc) return;
    float2 e2 = reinterpret_cast<const float2*>(emb + (size_t)code * Cc)[lane];
    u16 h0 = __bfloat16_as_ushort(__float2bfloat16(e2.x));
    u16 h1 = __bfloat16_as_ushort(__float2bfloat16(e2.y));
    g_Bbf[code * 32 + lane] = (u32)h0 | ((u32)h1 << 16);
    float s = e2.x * e2.x + e2.y * e2.y;
#pragma unroll
    for (int off = 16; off >= 1; off >>= 1)
        s += __shfl_xor_sync(0xffffffffu, s, off);
    if (lane == 0) {
        g_enorm[code] = s;
        atomicMax(&g_maxen, __float_as_uint(s));
    }
}

// --------------------- argmin + fused outputs/scatter ------------------------
// 128 persistent CTAs x 256 threads; CTA owns 128 tokens, scans 64 tiles of 128
// codes. 8 warps as 4(m) x 2(n); warp tile 32x64 via m16n8k16 + ldmatrix.
// 4-stage cp.async pipeline, ONE barrier per tile. Threshold = per-warp-half
// running row-min (>= global min => candidate superset preserved).
// After refine: fused z_q/z_q_st/idx outputs + EMA scatter (dw, counts).
#define ROWB 144
#define B_STAGE 18432
#define CAP 64

#define SM_EN     0          // 32768: ||e||^2 fp32
#define SM_ZF     32768      // 34816: z fp32 [128][68]
#define SM_ABF    67584      // 18432: bf16(-2z), 128 rows x 128B, stride 144
#define SM_B      86016      // 4 x 18432 stages (reused as zq tile after loop)
#define SM_MARG   159744     // 512 (reused as sidx after loop)
#define SM_CNT    160256     // 512
#define SM_CAND   160768     // 16384: u16 [128][CAP]
#define ARG_SMEM  177152
#define SM_ZQ     SM_B       // 128 x 65 floats = 33280 bytes (fits in stages)
#define SM_SIDX   SM_MARG

__global__ void __launch_bounds__(256, 1) argmin_kernel(
    const float* __restrict__ z_e,
    const float* __restrict__ emb,
    float* __restrict__ out)
{
    extern __shared__ char smem[];
    const u32 sb = smem_u32(smem);
    const int tid = threadIdx.x;
    const int lane = tid & 31;
    const int wid = tid >> 5;
    const int warp_m = wid >> 1, warp_n = wid & 1;
    const int gID = lane >> 2, tg = lane & 3;
    const int n0 = blockIdx.x * 128;
    const int b = n0 >> 10, hw0 = n0 & (HW - 1);

    float* en_s = reinterpret_cast<float*>(smem + SM_EN);
    float* zf   = reinterpret_cast<float*>(smem + SM_ZF);
    float* marg = reinterpret_cast<float*>(smem + SM_MARG);
    u32*   cnt  = reinterpret_cast<u32*>(smem + SM_CNT);
    u16*   cand = reinterpret_cast<u16*>(smem + SM_CAND);

    // ---- prologue: en, zf (transposed) ----
    for (int j = tid; j < Kc / 4; j += 256)
        reinterpret_cast<float4*>(en_s)[j] = reinterpret_cast<const float4*>(g_enorm)[j];
    for (int i = tid; i < Cc * 128; i += 256) {
        int c = i >> 7, t = i & 127;
        zf[t * 68 + c] = z_e[(size_t)b * Cc * HW + c * HW + hw0 + t];
    }
    if (tid < 128) cnt[tid] = 0u;
    __syncthreads();

    // bf16(-2z) tile for MMA A operand
    for (int i = tid; i < 128 * 32; i += 256) {
        int t = i >> 5, cp = i & 31;
        float x0 = -2.0f * zf[t * 68 + 2 * cp];
        float x1 = -2.0f * zf[t * 68 + 2 * cp + 1];
        u16 h0 = __bfloat16_as_ushort(__float2bfloat16(x0));
        u16 h1 = __bfloat16_as_ushort(__float2bfloat16(x1));
        reinterpret_cast<u32*>(smem + SM_ABF)[t * 36 + cp] = (u32)h0 | ((u32)h1 << 16);
    }
    // per-token margin: 2E bound for 1-term bf16 coarse distances
    if (tid < 128) {
        float s = 0.0f;
        for (int i = 0; i < Cc; i++) { float v = zf[tid * 68 + i]; s += v * v; }
        float maxe = sqrtf(__uint_as_float(g_maxen));
        marg[tid] = 0.0158f * sqrtf(s) * maxe + 0.003f;
    }

    // ---- 4-stage B pipeline ----
    auto loadB = [&](int ct, int s) {
        const char* gB = reinterpret_cast<const char*>(g_Bbf) + (size_t)ct * 128 * 128;
        u32 dst0 = sb + SM_B + s * B_STAGE;
        for (int j = tid; j < 1024; j += 256) {
            int r = j >> 3, c = j & 7;
            CP_ASYNC16(dst0 + r * ROWB + c * 16, gB + r * 128 + c * 16);
        }
    };
    loadB(0, 0); CP_COMMIT();
    loadB(1, 1); CP_COMMIT();
    loadB(2, 2); CP_COMMIT();
    __syncthreads();                      // marg/ABF visible before first use

    // per-warp running row-mins + margins (rows: warp_m*32 + mt*16 + h*8 + gID)
    float rmin[2][2], mg[2][2];
#pragma unroll
    for (int mt = 0; mt < 2; mt++)
#pragma unroll
        for (int h = 0; h < 2; h++) {
            rmin[mt][h] = CUDART_INF_F;
            mg[mt][h] = marg[warp_m * 32 + mt * 16 + h * 8 + gID];
        }

    const u32 aAddr0 = sb + SM_ABF + (u32)(warp_m * 32 + (lane & 15)) * ROWB
                     + ((u32)(lane >> 4) << 4);
    const u32 bAddrS = (u32)(warp_n * 64 + (lane & 15)) * ROWB + ((u32)(lane >> 4) << 4);

    for (int ct = 0; ct < 64; ct++) {
        CP_WAIT(2);
        __syncthreads();   // stage ct&3 visible to all; prev compute fully done

        float d[2][8][4];
#pragma unroll
        for (int mt = 0; mt < 2; mt++)
#pragma unroll
            for (int nt = 0; nt < 8; nt++)
#pragma unroll
                for (int i = 0; i < 4; i++) d[mt][nt][i] = 0.0f;

        const u32 bAddr = sb + SM_B + (u32)(ct & 3) * B_STAGE + bAddrS;
#pragma unroll
        for (int ks = 0; ks < 4; ks++) {
            u32 a[2][4];
            LDMX4(a[0], aAddr0 + ks * 32);
            LDMX4(a[1], aAddr0 + 16 * ROWB + ks * 32);
#pragma unroll
            for (int ntp = 0; ntp < 4; ntp++) {
                u32 bb[4];
                LDMX4(bb, bAddr + ntp * (16 * ROWB) + ks * 32);
                u32 be[2] = { bb[0], bb[2] };
                u32 bo[2] = { bb[1], bb[3] };
                mma16816(d[0][2 * ntp],     a[0], be);
                mma16816(d[0][2 * ntp + 1], a[0], bo);
                mma16816(d[1][2 * ntp],     a[1], be);
                mma16816(d[1][2 * ntp + 1], a[1], bo);
            }
        }

        // epilogue: add ||e||^2, fold local row-min (2 shuffles), candidates
        const float2* ent2 = reinterpret_cast<const float2*>(en_s + ct * 128 + warp_n * 64);
#pragma unroll
        for (int mt = 0; mt < 2; mt++) {
            float m0 = CUDART_INF_F, m1 = CUDART_INF_F;
#pragma unroll
            for (int nt = 0; nt < 8; nt++) {
                float2 ee = ent2[nt * 4 + tg];
                d[mt][nt][0] += ee.x; d[mt][nt][1] += ee.y;
                d[mt][nt][2] += ee.x; d[mt][nt][3] += ee.y;
                m0 = fminf(m0, fminf(d[mt][nt][0], d[mt][nt][1]));
                m1 = fminf(m1, fminf(d[mt][nt][2], d[mt][nt][3]));
            }
#pragma unroll
            for (int off = 1; off <= 2; off <<= 1) {
                m0 = fminf(m0, __shfl_xor_sync(0xffffffffu, m0, off));
                m1 = fminf(m1, __shfl_xor_sync(0xffffffffu, m1, off));
            }
            rmin[mt][0] = fminf(rmin[mt][0], m0);
            rmin[mt][1] = fminf(rmin[mt][1], m1);
            const float thr0 = rmin[mt][0] + mg[mt][0];
            const float thr1 = rmin[mt][1] + mg[mt][1];
            const int row0 = warp_m * 32 + mt * 16 + gID;
#pragma unroll
            for (int nt = 0; nt < 8; nt++) {
#pragma unroll
                for (int c = 0; c < 2; c++) {
                    int code = ct * 128 + warp_n * 64 + nt * 8 + tg * 2 + c;
                    if (d[mt][nt][c] <= thr0) {
                        u32 pos = atomicAdd(&cnt[row0], 1u);
                        if (pos < CAP) cand[row0 * CAP + pos] = (u16)code;
                    }
                    if (d[mt][nt][2 + c] <= thr1) {
                        u32 pos = atomicAdd(&cnt[row0 + 8], 1u);
                        if (pos < CAP) cand[(row0 + 8) * CAP + pos] = (u16)code;
                    }
                }
            }
        }

        if (ct + 3 < 64) { loadB(ct + 3, (ct + 3) & 3); CP_COMMIT(); }
    }
    __syncthreads();

    // ---- refine: exact fp32 over candidates (or full scan on overflow) ----
    int* sidx = reinterpret_cast<int*>(smem + SM_SIDX);   // marg dead now
    for (int tt = 0; tt < 16; tt++) {
        int t = wid * 16 + tt;
        u32 n = cnt[t];
        float bv = CUDART_INF_F;
        int bi = 0x7FFFFFFF;
        const float4* zf4 = reinterpret_cast<const float4*>(zf + t * 68);
        if (n <= CAP) {
            for (int j = lane; j < (int)n; j += 32) {
                int c = cand[t * CAP + j];
                const float4* e4 = reinterpret_cast<const float4*>(emb + (size_t)c * Cc);
                float dot = 0.0f;
#pragma unroll
                for (int i = 0; i < 16; i++) {
                    float4 zv = zf4[i], ev = e4[i];
                    dot = fmaf(zv.x, ev.x, dot);
                    dot = fmaf(zv.y, ev.y, dot);
                    dot = fmaf(zv.z, ev.z, dot);
                    dot = fmaf(zv.w, ev.w, dot);
                }
                float v = fmaf(-2.0f, dot, en_s[c]);
                if (v < bv || (v == bv && c < bi)) { bv = v; bi = c; }
            }
        } else {
            for (int c = lane; c < Kc; c += 32) {
                const float4* e4 = reinterpret_cast<const float4*>(emb + (size_t)c * Cc);
                float dot = 0.0f;
#pragma unroll
                for (int i = 0; i < 16; i++) {
                    float4 zv = zf4[i], ev = e4[i];
                    dot = fmaf(zv.x, ev.x, dot);
                    dot = fmaf(zv.y, ev.y, dot);
                    dot = fmaf(zv.z, ev.z, dot);
                    dot = fmaf(zv.w, ev.w, dot);
                }
                float v = fmaf(-2.0f, dot, en_s[c]);
                if (v < bv || (v == bv && c < bi)) { bv = v; bi = c; }
            }
        }
#pragma unroll
        for (int off = 16; off >= 1; off >>= 1) {
            float ov = __shfl_xor_sync(0xffffffffu, bv, off);
            int   oi = __shfl_xor_sync(0xffffffffu, bi, off);
            if (ov < bv || (ov == bv && oi < bi)) { bv = ov; bi = oi; }
        }
        if (lane == 0) sidx[t] = bi;
    }
    __syncthreads();

    // ---- fused outputs + EMA scatter ----
    // gather emb rows for owned tokens into zq tile (stride 65, conflict-free)
    float* zq = reinterpret_cast<float*>(smem + SM_ZQ);   // B stages dead now
    for (int r = wid; r < 128; r += 8) {
        int e = sidx[r];
        float2 v = reinterpret_cast<const float2*>(emb + (size_t)e * Cc)[lane];
        zq[r * 65 + 2 * lane]     = v.x;
        zq[r * 65 + 2 * lane + 1] = v.y;
    }
    if (tid < 128) {
        atomicAdd(&g_counts[sidx[tid]], 1.0f);
        out[O_IDX + n0 + tid] = (float)sidx[tid];
    }
    __syncthreads();

    // c-major coalesced stores + dw atomics
    const size_t obase = (size_t)b * Cc * HW + hw0;
    const int t = tid & 127;
    const int e = sidx[t];
#pragma unroll 4
    for (int iter = 0; iter < 32; iter++) {
        int c = 2 * iter + (tid >> 7);
        float zev = zf[t * 68 + c];
        float zqv = zq[t * 65 + c];
        float stv = zev + (zqv - zev);
        size_t o = obase + (size_t)c * HW + t;
        out[O_ZQST + o] = stv;
        out[O_ZQ + o]   = zqv;
        atomicAdd(&g_dw[e * Cc + c], zev);
    }
}

// --------------------- EMA blend + n reduction -------------------------------
__global__ void finalize1_kernel(const float* __restrict__ cs_in,
                                 const float* __restrict__ avg_in,
                                 float* __restrict__ out)
{
    int id = blockIdx.x * blockDim.x + threadIdx.x;   // over K*C/4
    if (id >= Kc * Cc / 4) return;
    float4 av = reinterpret_cast<const float4*>(avg_in)[id];
    float4 dw = reinterpret_cast<const float4*>(g_dw)[id];
    float4 r;
    r.x = DECAYF * av.x + ONE_MINUS_DECAYF * dw.x;
    r.y = DECAYF * av.y + ONE_MINUS_DECAYF * dw.y;
    r.z = DECAYF * av.z + ONE_MINUS_DECAYF * dw.z;
    r.w = DECAYF * av.w + ONE_MINUS_DECAYF * dw.w;
    reinterpret_cast<float4*>(out + O_AVG)[id] = r;

    if (id < Kc / 4) {
        float4 cv = reinterpret_cast<const float4*>(cs_in)[id];
        float4 ct = reinterpret_cast<const float4*>(g_counts)[id];
        float4 cs;
        cs.x = DECAYF * cv.x + ONE_MINUS_DECAYF * ct.x;
        cs.y = DECAYF * cv.y + ONE_MINUS_DECAYF * ct.y;
        cs.z = DECAYF * cv.z + ONE_MINUS_DECAYF * ct.z;
        cs.w = DECAYF * cv.w + ONE_MINUS_DECAYF * ct.w;
        reinterpret_cast<float4*>(out + O_CS)[id] = cs;
        float local = cs.x + cs.y + cs.z + cs.w;
#pragma unroll
        for (int off = 16; off >= 1; off >>= 1)
            local += __shfl_xor_sync(0xffffffffu, local, off);
        if ((threadIdx.x & 31) == 0) atomicAdd(g_n, local);
    }
}

// --------------------- normalized embedding ----------------------------------
__global__ void finalize2_kernel(float* __restrict__ out) {
    int id = blockIdx.x * blockDim.x + threadIdx.x;   // over K*C/4
    if (id >= Kc * Cc / 4) return;
    int k = id >> 4;
    float n = g_n[0];
    float csv = out[O_CS + k];
    float cs = (csv + EPSF) / (n + (float)Kc * EPSF) * n;
    float inv = 1.0f / cs;
    float4 av = reinterpret_cast<const float4*>(out + O_AVG)[id];
    float4 r;
    r.x = av.x * inv; r.y = av.y * inv; r.z = av.z * inv; r.w = av.w * inv;
    reinterpret_cast<float4*>(out + O_EMB)[id] = r;
}

// --------------------- launcher ---------------------------------------------
extern "C" void kernel_launch(void* const* d_in, const int* in_sizes, int n_in,
                              void* d_out, int out_size)
{
    const float* z_e = (const float*)d_in[0];
    const float* emb = (const float*)d_in[1];
    const float* cs  = (const float*)d_in[2];
    const float* avg = (const float*)d_in[3];
    float* out = (float*)d_out;

    cudaFuncSetAttribute(argmin_kernel,
                         cudaFuncAttributeMaxDynamicSharedMemorySize, ARG_SMEM);

    prep_kernel<<<Kc * 32 / 256, 256>>>(emb);
    argmin_kernel<<<Ntok / 128, 256, ARG_SMEM>>>(z_e, emb, out);
    finalize1_kernel<<<(Kc * Cc / 4 + 255) / 256, 256>>>(cs, avg, out);
    finalize2_kernel<<<(Kc * Cc / 4 + 255) / 256, 256>>>(out);
}

// round 15
// speedup vs baseline: 1.8053x; 1.0287x over previous
#include <cuda_runtime.h>
#include <cuda_bf16.h>
#include <math_constants.h>
#include <cstdint>

typedef unsigned long long u64;
typedef unsigned int       u32;
typedef unsigned short     u16;

// Problem constants
#define Bb 16
#define Cc 64
#define HW 1024
#define Ntok 16384
#define Kc 8192
#define DECAYF 0.99f
#define ONE_MINUS_DECAYF 0.01f
#define EPSF 1e-5f

// Output layout (float32, reference-return order)
#define O_ZQST 0
#define O_IDX  1048576
#define O_ZQ   1064960
#define O_EMB  2113536
#define O_CS   2637824
#define O_AVG  2646016

// --------------------- scratch (device globals) ------------------------------
__device__ u32   g_Bbf[Kc * 32];    // bf16 codebook, code-major rows of 64 bf16
__device__ float g_enorm[Kc];
__device__ u32   g_maxen;           // bits of max ||e||^2 (positive float)
__device__ float g_counts[Kc];
__device__ float g_dw[Kc * Cc];
__device__ float g_part[32];        // per-block partial sums of cs_in

// --------------------- helpers ----------------------------------------------
__device__ __forceinline__ u32 smem_u32(const void* p) {
    u32 a;
    asm("{ .reg .u64 t; cvta.to.shared.u64 t, %1; cvt.u32.u64 %0, t; }" : "=r"(a) : "l"(p));
    return a;
}
#define CP_ASYNC16(dst, src) \
    asm volatile("cp.async.cg.shared.global [%0], [%1], 16;" :: "r"(dst), "l"(src))
#define CP_COMMIT() asm volatile("cp.async.commit_group;" ::: "memory")
#define CP_WAIT(n)  asm volatile("cp.async.wait_group %0;" :: "n"(n) : "memory")

#define LDMX4(r, addr) \
    asm volatile("ldmatrix.sync.aligned.m8n8.x4.shared.b16 {%0,%1,%2,%3}, [%4];" \
        : "=r"((r)[0]), "=r"((r)[1]), "=r"((r)[2]), "=r"((r)[3]) : "r"(addr))

__device__ __forceinline__ void mma16816(float* d, const u32* a, const u32* b) {
    asm volatile("mma.sync.aligned.m16n8k16.row.col.f32.bf16.bf16.f32 "
        "{%0,%1,%2,%3}, {%4,%5,%6,%7}, {%8,%9}, {%0,%1,%2,%3};"
        : "+f"(d[0]), "+f"(d[1]), "+f"(d[2]), "+f"(d[3])
        : "r"(a[0]), "r"(a[1]), "r"(a[2]), "r"(a[3]), "r"(b[0]), "r"(b[1]));
}

// --------------------- prep: zero scratch + ||e||^2 + bf16 codebook ----------
// grid = 1024 x 256 threads (warp per code); blocks 0..31 also reduce cs_in.
__global__ void __launch_bounds__(256) prep_kernel(const float* __restrict__ emb,
                                                   const float* __restrict__ cs_in) {
    __shared__ float red[8];
    int tid = threadIdx.x;
    int gtid = blockIdx.x * 256 + tid;
    // zero g_dw (131072 float4), g_counts
    if (gtid < Kc * Cc / 4) reinterpret_cast<float4*>(g_dw)[gtid] = make_float4(0, 0, 0, 0);
    if (gtid < Kc) g_counts[gtid] = 0.0f;
    if (gtid == 0) g_maxen = 0u;

    // partial sums of cs_in (blocks 0..31 cover all 8192 elements)
    if (blockIdx.x < 32) {
        float v = cs_in[gtid];
#pragma unroll
        for (int off = 16; off >= 1; off >>= 1)
            v += __shfl_xor_sync(0xffffffffu, v, off);
        if ((tid & 31) == 0) red[tid >> 5] = v;
        __syncthreads();
        if (tid == 0) {
            float s = 0.0f;
#pragma unroll
            for (int i = 0; i < 8; i++) s += red[i];
            g_part[blockIdx.x] = s;
        }
    }

    int code = gtid >> 5, lane = gtid & 31;
    if (code >= Kc) return;
    float2 e2 = reinterpret_cast<const float2*>(emb + (size_t)code * Cc)[lane];
    u16 h0 = __bfloat16_as_ushort(__float2bfloat16(e2.x));
    u16 h1 = __bfloat16_as_ushort(__float2bfloat16(e2.y));
    g_Bbf[code * 32 + lane] = (u32)h0 | ((u32)h1 << 16);
    float s = e2.x * e2.x + e2.y * e2.y;
#pragma unroll
    for (int off = 16; off >= 1; off >>= 1)
        s += __shfl_xor_sync(0xffffffffu, s, off);
    if (lane == 0) {
        g_enorm[code] = s;
        atomicMax(&g_maxen, __float_as_uint(s));
    }
}

// --------------------- argmin + fused outputs/scatter ------------------------
// 128 persistent CTAs x 256 threads; CTA owns 128 tokens, scans 64 tiles of 128
// codes. 8 warps as 4(m) x 2(n); warp tile 32x64 via m16n8k16 + ldmatrix.
// 4-stage cp.async pipeline, ONE barrier per tile. Threshold = per-warp-half
// running row-min (>= global min => candidate superset preserved).
// Warp-uniform skip of the candidate scan when the tile provably has none.
#define ROWB 144
#define B_STAGE 18432
#define CAP 64

#define SM_EN     0          // 32768: ||e||^2 fp32
#define SM_ZF     32768      // 34816: z fp32 [128][68]
#define SM_ABF    67584      // 18432: bf16(-2z), 128 rows x 128B, stride 144
#define SM_B      86016      // 4 x 18432 stages (reused as zq tile after loop)
#define SM_MARG   159744     // 512 (reused as sidx after loop)
#define SM_CNT    160256     // 512
#define SM_CAND   160768     // 16384: u16 [128][CAP]
#define ARG_SMEM  177152
#define SM_ZQ     SM_B       // 128 x 65 floats = 33280 bytes (fits in stages)
#define SM_SIDX   SM_MARG

__global__ void __launch_bounds__(256, 1) argmin_kernel(
    const float* __restrict__ z_e,
    const float* __restrict__ emb,
    float* __restrict__ out)
{
    extern __shared__ char smem[];
    const u32 sb = smem_u32(smem);
    const int tid = threadIdx.x;
    const int lane = tid & 31;
    const int wid = tid >> 5;
    const int warp_m = wid >> 1, warp_n = wid & 1;
    const int gID = lane >> 2, tg = lane & 3;
    const int n0 = blockIdx.x * 128;
    const int b = n0 >> 10, hw0 = n0 & (HW - 1);

    float* en_s = reinterpret_cast<float*>(smem + SM_EN);
    float* zf   = reinterpret_cast<float*>(smem + SM_ZF);
    float* marg = reinterpret_cast<float*>(smem + SM_MARG);
    u32*   cnt  = reinterpret_cast<u32*>(smem + SM_CNT);
    u16*   cand = reinterpret_cast<u16*>(smem + SM_CAND);

    // ---- prologue: en, zf (transposed) ----
    for (int j = tid; j < Kc / 4; j += 256)
        reinterpret_cast<float4*>(en_s)[j] = reinterpret_cast<const float4*>(g_enorm)[j];
    for (int i = tid; i < Cc * 128; i += 256) {
        int c = i >> 7, t = i & 127;
        zf[t * 68 + c] = z_e[(size_t)b * Cc * HW + c * HW + hw0 + t];
    }
    if (tid < 128) cnt[tid] = 0u;
    __syncthreads();

    // bf16(-2z) tile for MMA A operand
    for (int i = tid; i < 128 * 32; i += 256) {
        int t = i >> 5, cp = i & 31;
        float x0 = -2.0f * zf[t * 68 + 2 * cp];
        float x1 = -2.0f * zf[t * 68 + 2 * cp + 1];
        u16 h0 = __bfloat16_as_ushort(__float2bfloat16(x0));
        u16 h1 = __bfloat16_as_ushort(__float2bfloat16(x1));
        reinterpret_cast<u32*>(smem + SM_ABF)[t * 36 + cp] = (u32)h0 | ((u32)h1 << 16);
    }
    // per-token margin: 2E bound for 1-term bf16 coarse distances
    if (tid < 128) {
        float s = 0.0f;
        for (int i = 0; i < Cc; i++) { float v = zf[tid * 68 + i]; s += v * v; }
        float maxe = sqrtf(__uint_as_float(g_maxen));
        marg[tid] = 0.0158f * sqrtf(s) * maxe + 0.003f;
    }

    // ---- 4-stage B pipeline ----
    auto loadB = [&](int ct, int s) {
        const char* gB = reinterpret_cast<const char*>(g_Bbf) + (size_t)ct * 128 * 128;
        u32 dst0 = sb + SM_B + s * B_STAGE;
        for (int j = tid; j < 1024; j += 256) {
            int r = j >> 3, c = j & 7;
            CP_ASYNC16(dst0 + r * ROWB + c * 16, gB + r * 128 + c * 16);
        }
    };
    loadB(0, 0); CP_COMMIT();
    loadB(1, 1); CP_COMMIT();
    loadB(2, 2); CP_COMMIT();
    __syncthreads();                      // marg/ABF visible before first use

    // per-warp running row-mins + margins (rows: warp_m*32 + mt*16 + h*8 + gID)
    float rmin[2][2], mg[2][2];
#pragma unroll
    for (int mt = 0; mt < 2; mt++)
#pragma unroll
        for (int h = 0; h < 2; h++) {
            rmin[mt][h] = CUDART_INF_F;
            mg[mt][h] = marg[warp_m * 32 + mt * 16 + h * 8 + gID];
        }

    const u32 aAddr0 = sb + SM_ABF + (u32)(warp_m * 32 + (lane & 15)) * ROWB
                     + ((u32)(lane >> 4) << 4);
    const u32 bAddrS = (u32)(warp_n * 64 + (lane & 15)) * ROWB + ((u32)(lane >> 4) << 4);

    for (int ct = 0; ct < 64; ct++) {
        CP_WAIT(2);
        __syncthreads();   // stage ct&3 visible to all; prev compute fully done

        float d[2][8][4];
#pragma unroll
        for (int mt = 0; mt < 2; mt++)
#pragma unroll
            for (int nt = 0; nt < 8; nt++)
#pragma unroll
                for (int i = 0; i < 4; i++) d[mt][nt][i] = 0.0f;

        const u32 bAddr = sb + SM_B + (u32)(ct & 3) * B_STAGE + bAddrS;
#pragma unroll
        for (int ks = 0; ks < 4; ks++) {
            u32 a[2][4];
            LDMX4(a[0], aAddr0 + ks * 32);
            LDMX4(a[1], aAddr0 + 16 * ROWB + ks * 32);
#pragma unroll
            for (int ntp = 0; ntp < 4; ntp++) {
                u32 bb[4];
                LDMX4(bb, bAddr + ntp * (16 * ROWB) + ks * 32);
                u32 be[2] = { bb[0], bb[2] };
                u32 bo[2] = { bb[1], bb[3] };
                mma16816(d[0][2 * ntp],     a[0], be);
                mma16816(d[0][2 * ntp + 1], a[0], bo);
                mma16816(d[1][2 * ntp],     a[1], be);
                mma16816(d[1][2 * ntp + 1], a[1], bo);
            }
        }

        // prefetch next stage ASAP — independent of the epilogue below
        if (ct + 3 < 64) { loadB(ct + 3, (ct + 3) & 3); CP_COMMIT(); }

        // epilogue: add ||e||^2, fold exact tile row-min (2 shuffles), then
        // candidate scan ONLY if this tile can contain one (warp-uniform skip)
        const float2* ent2 = reinterpret_cast<const float2*>(en_s + ct * 128 + warp_n * 64);
#pragma unroll
        for (int mt = 0; mt < 2; mt++) {
            float m0 = CUDART_INF_F, m1 = CUDART_INF_F;
#pragma unroll
            for (int nt = 0; nt < 8; nt++) {
                float2 ee = ent2[nt * 4 + tg];
                d[mt][nt][0] += ee.x; d[mt][nt][1] += ee.y;
                d[mt][nt][2] += ee.x; d[mt][nt][3] += ee.y;
                m0 = fminf(m0, fminf(d[mt][nt][0], d[mt][nt][1]));
                m1 = fminf(m1, fminf(d[mt][nt][2], d[mt][nt][3]));
            }
#pragma unroll
            for (int off = 1; off <= 2; off <<= 1) {
                m0 = fminf(m0, __shfl_xor_sync(0xffffffffu, m0, off));
                m1 = fminf(m1, __shfl_xor_sync(0xffffffffu, m1, off));
            }
            rmin[mt][0] = fminf(rmin[mt][0], m0);
            rmin[mt][1] = fminf(rmin[mt][1], m1);
            const float thr0 = rmin[mt][0] + mg[mt][0];
            const float thr1 = rmin[mt][1] + mg[mt][1];
            // m0/m1 are EXACT row-mins of this tile: if above threshold for all
            // lanes, no element can qualify -> skip the 32-element scan.
            if (__any_sync(0xffffffffu, (m0 <= thr0) || (m1 <= thr1))) {
                const int row0 = warp_m * 32 + mt * 16 + gID;
#pragma unroll
                for (int nt = 0; nt < 8; nt++) {
#pragma unroll
                    for (int c = 0; c < 2; c++) {
                        int code = ct * 128 + warp_n * 64 + nt * 8 + tg * 2 + c;
                        if (d[mt][nt][c] <= thr0) {
                            u32 pos = atomicAdd(&cnt[row0], 1u);
                            if (pos < CAP) cand[row0 * CAP + pos] = (u16)code;
                        }
                        if (d[mt][nt][2 + c] <= thr1) {
                            u32 pos = atomicAdd(&cnt[row0 + 8], 1u);
                            if (pos < CAP) cand[(row0 + 8) * CAP + pos] = (u16)code;
                        }
                    }
                }
            }
        }
    }
    __syncthreads();

    // ---- refine: exact fp32 over candidates (or full scan on overflow) ----
    int* sidx = reinterpret_cast<int*>(smem + SM_SIDX);   // marg dead now
    for (int tt = 0; tt < 16; tt++) {
        int t = wid * 16 + tt;
        u32 n = cnt[t];
        float bv = CUDART_INF_F;
        int bi = 0x7FFFFFFF;
        const float4* zf4 = reinterpret_cast<const float4*>(zf + t * 68);
        if (n <= CAP) {
            for (int j = lane; j < (int)n; j += 32) {
                int c = cand[t * CAP + j];
                const float4* e4 = reinterpret_cast<const float4*>(emb + (size_t)c * Cc);
                float dot = 0.0f;
#pragma unroll
                for (int i = 0; i < 16; i++) {
                    float4 zv = zf4[i], ev = e4[i];
                    dot = fmaf(zv.x, ev.x, dot);
                    dot = fmaf(zv.y, ev.y, dot);
                    dot = fmaf(zv.z, ev.z, dot);
                    dot = fmaf(zv.w, ev.w, dot);
                }
                float v = fmaf(-2.0f, dot, en_s[c]);
                if (v < bv || (v == bv && c < bi)) { bv = v; bi = c; }
            }
        } else {
            for (int c = lane; c < Kc; c += 32) {
                const float4* e4 = reinterpret_cast<const float4*>(emb + (size_t)c * Cc);
                float dot = 0.0f;
#pragma unroll
                for (int i = 0; i < 16; i++) {
                    float4 zv = zf4[i], ev = e4[i];
                    dot = fmaf(zv.x, ev.x, dot);
                    dot = fmaf(zv.y, ev.y, dot);
                    dot = fmaf(zv.z, ev.z, dot);
                    dot = fmaf(zv.w, ev.w, dot);
                }
                float v = fmaf(-2.0f, dot, en_s[c]);
                if (v < bv || (v == bv && c < bi)) { bv = v; bi = c; }
            }
        }
#pragma unroll
        for (int off = 16; off >= 1; off >>= 1) {
            float ov = __shfl_xor_sync(0xffffffffu, bv, off);
            int   oi = __shfl_xor_sync(0xffffffffu, bi, off);
            if (ov < bv || (ov == bv && oi < bi)) { bv = ov; bi = oi; }
        }
        if (lane == 0) sidx[t] = bi;
    }
    __syncthreads();

    // ---- fused outputs + EMA scatter ----
    // gather emb rows for owned tokens into zq tile (stride 65, conflict-free)
    float* zq = reinterpret_cast<float*>(smem + SM_ZQ);   // B stages dead now
    for (int r = wid; r < 128; r += 8) {
        int e = sidx[r];
        float2 v = reinterpret_cast<const float2*>(emb + (size_t)e * Cc)[lane];
        zq[r * 65 + 2 * lane]     = v.x;
        zq[r * 65 + 2 * lane + 1] = v.y;
    }
    if (tid < 128) {
        atomicAdd(&g_counts[sidx[tid]], 1.0f);
        out[O_IDX + n0 + tid] = (float)sidx[tid];
    }
    __syncthreads();

    // c-major coalesced stores + dw atomics
    const size_t obase = (size_t)b * Cc * HW + hw0;
    const int t = tid & 127;
    const int e = sidx[t];
#pragma unroll 4
    for (int iter = 0; iter < 32; iter++) {
        int c = 2 * iter + (tid >> 7);
        float zev = zf[t * 68 + c];
        float zqv = zq[t * 65 + c];
        float stv = zev + (zqv - zev);
        size_t o = obase + (size_t)c * HW + t;
        out[O_ZQST + o] = stv;
        out[O_ZQ + o]   = zqv;
        atomicAdd(&g_dw[e * Cc + c], zev);
    }
}

// --------------------- fused finalize: cs, avg, embedding --------------------
__global__ void __launch_bounds__(256) finalize_kernel(
    const float* __restrict__ cs_in,
    const float* __restrict__ avg_in,
    float* __restrict__ out)
{
    __shared__ float sn;
    int tid = threadIdx.x;
    if (tid < 32) {
        float v = g_part[tid];
#pragma unroll
        for (int off = 16; off >= 1; off >>= 1)
            v += __shfl_xor_sync(0xffffffffu, v, off);
        if (tid == 0)
            sn = DECAYF * v + ONE_MINUS_DECAYF * (float)Ntok;   // n = sum(new_cs)
    }
    __syncthreads();
    const float n = sn;

    int id = blockIdx.x * 256 + tid;   // over K*C/4
    if (id >= Kc * Cc / 4) return;

    float4 av = reinterpret_cast<const float4*>(avg_in)[id];
    float4 dw = reinterpret_cast<const float4*>(g_dw)[id];
    float4 r;
    r.x = DECAYF * av.x + ONE_MINUS_DECAYF * dw.x;
    r.y = DECAYF * av.y + ONE_MINUS_DECAYF * dw.y;
    r.z = DECAYF * av.z + ONE_MINUS_DECAYF * dw.z;
    r.w = DECAYF * av.w + ONE_MINUS_DECAYF * dw.w;
    reinterpret_cast<float4*>(out + O_AVG)[id] = r;

    int k = id >> 4;
    float csv = DECAYF * cs_in[k] + ONE_MINUS_DECAYF * g_counts[k];
    float cs = (csv + EPSF) / (n + (float)Kc * EPSF) * n;
    float inv = 1.0f / cs;
    float4 em;
    em.x = r.x * inv; em.y = r.y * inv; em.z = r.z * inv; em.w = r.w * inv;
    reinterpret_cast<float4*>(out + O_EMB)[id] = em;

    if (id < Kc / 4) {
        float4 cv = reinterpret_cast<const float4*>(cs_in)[id];
        float4 ct = reinterpret_cast<const float4*>(g_counts)[id];
        float4 cso;
        cso.x = DECAYF * cv.x + ONE_MINUS_DECAYF * ct.x;
        cso.y = DECAYF * cv.y + ONE_MINUS_DECAYF * ct.y;
        cso.z = DECAYF * cv.z + ONE_MINUS_DECAYF * ct.z;
        cso.w = DECAYF * cv.w + ONE_MINUS_DECAYF * ct.w;
        reinterpret_cast<float4*>(out + O_CS)[id] = cso;
    }
}

// --------------------- launcher ---------------------------------------------
extern "C" void kernel_launch(void* const* d_in, const int* in_sizes, int n_in,
                              void* d_out, int out_size)
{
    const float* z_e = (const float*)d_in[0];
    const float* emb = (const float*)d_in[1];
    const float* cs  = (const float*)d_in[2];
    const float* avg = (const float*)d_in[3];
    float* out = (float*)d_out;

    cudaFuncSetAttribute(argmin_kernel,
                         cudaFuncAttributeMaxDynamicSharedMemorySize, ARG_SMEM);

    prep_kernel<<<Kc * 32 / 256, 256>>>(emb, cs);
    argmin_kernel<<<Ntok / 128, 256, ARG_SMEM>>>(z_e, emb, out);
    finalize_kernel<<<(Kc * Cc / 4 + 255) / 256, 256>>>(cs, avg, out);
}